// round 11
// baseline (speedup 1.0000x reference)
#include <cuda_runtime.h>
#include <cuda_fp16.h>
#include <cstdint>

// ---------------------------------------------------------------------------
// DLKA conv block. Dense GEMMs on mma.sync fp16 (conv3 3-pass hi/lo; branch
// 1-pass). 1-pass convs: 4-deep B pipeline + double-buffered A, one barrier
// per tap. fp16 offsets/u, fused g1+p2, 8-thread/px fp16 deform.
// ---------------------------------------------------------------------------

static constexpr int BB   = 4;
static constexpr int CH   = 64;
static constexpr int IH   = 256;
static constexpr int IW   = 256;
static constexpr int PIX  = IH * IW;
static constexpr int NPIX = BB * PIX;

// ----------------------------- device scratch ------------------------------
__device__ float g_h  [(size_t)NPIX * CH];    // conv3 raw out (fp32, shortcut)
__device__ __half g_off[(size_t)NPIX * 112];  // offset maps (fp16)
__device__ __half g_bfh[(size_t)NPIX * CH], g_bfl[(size_t)NPIX * CH];
__device__ __half g_b2h[(size_t)NPIX * CH];
__device__ __half g_w3h[9  * 64  * 64], g_w3l[9 * 64 * 64];
__device__ __half g_w5h[25 * 64  * 64];
__device__ __half g_w7h[49 * 112 * 64];
__device__ __half g_wp1h[4 * 64 * 64];
__device__ __half g_wg1h[64 * 64];
__device__ __half g_wp2h[64 * 64];
__device__ float g_bp1[256];
__device__ float g_part[BB * 32 * 64 * 2];
__device__ float g_stats[512];

// ----------------------------- helpers -------------------------------------
__device__ __forceinline__ uint32_t smem_u32(const void* p) {
    uint32_t a;
    asm("{ .reg .u64 t; cvta.to.shared.u64 t, %1; cvt.u32.u64 %0, t; }"
        : "=r"(a) : "l"(p));
    return a;
}
__device__ __host__ __forceinline__ uint32_t swz128(uint32_t off) {
    return off ^ ((off >> 3) & 0x70);
}
__device__ __forceinline__ void ldm4(uint32_t* r, uint32_t addr) {
    asm volatile("ldmatrix.sync.aligned.m8n8.x4.shared.b16 {%0,%1,%2,%3}, [%4];"
                 : "=r"(r[0]), "=r"(r[1]), "=r"(r[2]), "=r"(r[3]) : "r"(addr));
}
__device__ __forceinline__ void mma16816(float* c, const uint32_t* a,
                                         uint32_t b0, uint32_t b1) {
    asm volatile(
        "mma.sync.aligned.m16n8k16.row.col.f32.f16.f16.f32 "
        "{%0,%1,%2,%3}, {%4,%5,%6,%7}, {%8,%9}, {%0,%1,%2,%3};"
        : "+f"(c[0]), "+f"(c[1]), "+f"(c[2]), "+f"(c[3])
        : "r"(a[0]), "r"(a[1]), "r"(a[2]), "r"(a[3]), "r"(b0), "r"(b1));
}
__device__ __forceinline__ void cpa16(uint32_t dst, const void* src, int sz) {
    asm volatile("cp.async.cg.shared.global [%0], [%1], 16, %2;"
                 :: "r"(dst), "l"(src), "r"(sz) : "memory");
}
__device__ __forceinline__ void cpa_commit() {
    asm volatile("cp.async.commit_group;" ::: "memory");
}
template <int N>
__device__ __forceinline__ void cpa_wait() {
    asm volatile("cp.async.wait_group %0;" :: "n"(N) : "memory");
}
__device__ __forceinline__ float gelu_exact(float v) {
    return 0.5f * v * (1.f + erff(v * 0.70710678118654752440f));
}
__device__ __forceinline__ void store_h2(__half* p, size_t idx, float v0, float v1) {
    *(__half2*)(p + idx) = __floats2half2_rn(v0, v1);
}

// ---------------- NCHW -> NHWC transpose to fp16 hi/lo ---------------------
__global__ void k_x2bf(const float* __restrict__ in) {
    __shared__ float tile[32][33];
    int b = blockIdx.z, p0 = blockIdx.x * 32, c0 = blockIdx.y * 32;
    int tx = threadIdx.x, ty = threadIdx.y;
#pragma unroll
    for (int i = 0; i < 4; i++)
        tile[ty + 8 * i][tx] =
            in[((size_t)(b * CH + c0 + ty + 8 * i)) * PIX + p0 + tx];
    __syncthreads();
#pragma unroll
    for (int i = 0; i < 4; i++) {
        float v = tile[tx][ty + 8 * i];
        size_t ix = ((size_t)b * PIX + p0 + ty + 8 * i) * CH + c0 + tx;
        __half h = __float2half_rn(v);
        g_bfh[ix] = h;
        g_bfl[ix] = __float2half_rn(v - __half2float(h));
    }
}

// ------- weight prep: [o][c][kh][kw] -> pre-swizzled fp16 [tap][o][c] ------
__global__ void k_prepw(const float* __restrict__ w, __half* __restrict__ wh,
                        __half* __restrict__ wl, int COUT, int CS, int KK) {
    int idx = blockIdx.x * 256 + threadIdx.x;
    int total = KK * CS * 64;
    if (idx >= total) return;
    int tap = idx / (CS * 64);
    int r = idx - tap * CS * 64;
    int o = r >> 6, c = r & 63;
    float v = (o < COUT) ? w[((size_t)o * 64 + c) * KK + tap] : 0.f;
    __half h = __float2half_rn(v);
    uint32_t so = swz128((uint32_t)(o * 128 + c * 2));
    size_t base = (size_t)tap * CS * 128;
    *(__half*)((char*)wh + base + so) = h;
    if (wl)
        *(__half*)((char*)wl + base + so) = __float2half_rn(v - __half2float(h));
}

// ------- p1 weight fold: w'[b,o,c] = w[o,c]*rstd[b,c]; bias fold -----------
__global__ void k_prepp1(const float* __restrict__ w, const float* __restrict__ bias) {
    int b = blockIdx.x >> 6, o = blockIdx.x & 63;
    int c = threadIdx.x;
    float r = g_stats[256 + b * 64 + c];
    float m = g_stats[b * 64 + c];
    float wv = w[o * 64 + c] * r;
    uint32_t so = swz128((uint32_t)(o * 128 + c * 2));
    *(__half*)((char*)g_wp1h + (size_t)b * 64 * 128 + so) = __float2half_rn(wv);
    __shared__ float red[64];
    red[c] = wv * m;
    __syncthreads();
    if (c < 32) red[c] += red[c + 32];
    __syncwarp();
    if (c < 16) red[c] += red[c + 16];
    __syncwarp();
    if (c < 8)  red[c] += red[c + 8];
    __syncwarp();
    if (c < 4)  red[c] += red[c + 4];
    __syncwarp();
    if (c == 0)
        g_bp1[b * 64 + o] = bias[o] - (red[0] + red[1] + red[2] + red[3]);
}

// ---------------- mma.sync conv with cp.async pipeline ---------------------
// NPASS==3 (conv3): 2-buffer B, hi/lo A, 2 syncs/tap (proven path).
// NPASS==1 (branch convs): 4-buffer B lookahead-2, double-buffered A staged
// one ky ahead, ONE sync per tap, uniform wait_group<2>.
// OMODE 0: fp32 out (stride 64) + fp16 copy. OMODE 1: fp16 out (stride OSTR).
template <int COUT, int CS, int NFRAG, int K, int PAD, int DIL, bool HASB,
          int OSTR, int NPASS, int OMODE>
__global__ void __launch_bounds__(256, 2) k_mmaconv(
    const __half* __restrict__ Ah, const __half* __restrict__ Al,
    const __half* __restrict__ Wh, const __half* __restrict__ Wl,
    const float* __restrict__ bias, void* __restrict__ outv,
    __half* __restrict__ obh) {
    constexpr int KK   = K * K;
    constexpr int NQ   = (NFRAG + 1) / 2;
    constexpr int WPX  = 128 + (K - 1) * DIL;
    constexpr int ASZ  = ((WPX * 128 + 1023) / 1024) * 1024;
    constexpr int BPB  = CS * 128 * (NPASS == 3 ? 2 : 1);
    constexpr int NBUF = (NPASS == 3 ? 2 : 4);
    constexpr int A_OFF = NBUF * BPB;
    constexpr int BIAS_OFF = A_OFF + 2 * ASZ;
    extern __shared__ __align__(128) char smem[];
    uint32_t sb = smem_u32(smem);
    const int tid  = threadIdx.x;
    const int wid  = tid >> 5, lane = tid & 31;
    const int b    = blockIdx.y;
    const int y0   = blockIdx.x >> 1;
    const int xb   = (blockIdx.x & 1) * 128;
    const int m0   = (wid & 3) * 32;
    const int n0   = (wid >> 2) * (NFRAG * 8);
    const int lrow = (lane & 7) + (lane & 8);
    const int lc16 = (lane & 16);
    const size_t bbase = ((size_t)b << 16);

    float* bsm = (float*)(smem + BIAS_OFF);
    for (int i = tid; i < OSTR; i += 256)
        bsm[i] = (HASB && i < COUT) ? bias[i] : 0.f;

    float acc[2][NFRAG][4];
#pragma unroll
    for (int mf = 0; mf < 2; mf++)
#pragma unroll
        for (int nf = 0; nf < NFRAG; nf++)
#pragma unroll
            for (int j = 0; j < 4; j++) acc[mf][nf][j] = 0.f;

    auto stageB = [&](int tap, int buf) {
        const char* sh = (const char*)Wh + (size_t)tap * CS * 128;
        uint32_t d = sb + buf * BPB;
        for (int idx = tid * 16; idx < CS * 128; idx += 256 * 16) {
            cpa16(d + idx, sh + idx, 16);
            if (NPASS == 3)
                cpa16(d + CS * 128 + idx,
                      (const char*)Wl + (size_t)tap * CS * 128 + idx, 16);
        }
    };
    auto stageA = [&](int ky, int abuf) {
        const int ysrc = y0 + ky * DIL - PAD;
        const bool yok = (unsigned)ysrc < 256u;
        const size_t rowb = (bbase + (size_t)ysrc * 256) * 128;
        uint32_t dbase = sb + A_OFF + abuf * ASZ;
        for (int i = tid; i < WPX * 8; i += 256) {
            int p = i >> 3, u = i & 7;
            int xs = xb - PAD + p;
            bool ok = yok && ((unsigned)xs < 256u);
            size_t off = ok ? rowb + (size_t)xs * 128 + u * 16 : 0;
            int sz = ok ? 16 : 0;
            uint32_t d = swz128((uint32_t)(p * 128 + u * 16));
            cpa16(dbase + d, (const char*)Ah + off, sz);
            if (NPASS == 3)
                cpa16(sb + A_OFF + ASZ + d, (const char*)Al + off, sz);
        }
    };

    auto compute_tap = [&](int kx, uint32_t AbH, uint32_t AbL, uint32_t BbH,
                           uint32_t BbL) {
        const int kxo = kx * DIL;
#pragma unroll
        for (int kc = 0; kc < 4; kc++) {
            uint32_t ah0[4], ah1[4], al0[4], al1[4];
            uint32_t a_off0 = swz128((uint32_t)((kxo + m0 + lrow) * 128 + kc * 32 + lc16));
            uint32_t a_off1 = swz128((uint32_t)((kxo + m0 + 16 + lrow) * 128 + kc * 32 + lc16));
            ldm4(ah0, AbH + a_off0); ldm4(ah1, AbH + a_off1);
            if (NPASS == 3) { ldm4(al0, AbL + a_off0); ldm4(al1, AbL + a_off1); }
#pragma unroll
            for (int q = 0; q < NQ; q++) {
                uint32_t bh[4], bl[4];
                uint32_t b_off = swz128((uint32_t)((n0 + 16 * q + lrow) * 128 + kc * 32 + lc16));
                ldm4(bh, BbH + b_off);
                if (NPASS == 3) ldm4(bl, BbL + b_off);
                mma16816(acc[0][2 * q], ah0, bh[0], bh[2]);
                mma16816(acc[1][2 * q], ah1, bh[0], bh[2]);
                if (NPASS == 3) {
                    mma16816(acc[0][2 * q], ah0, bl[0], bl[2]);
                    mma16816(acc[1][2 * q], ah1, bl[0], bl[2]);
                    mma16816(acc[0][2 * q], al0, bh[0], bh[2]);
                    mma16816(acc[1][2 * q], al1, bh[0], bh[2]);
                }
                if (2 * q + 1 < NFRAG) {
                    mma16816(acc[0][2 * q + 1], ah0, bh[1], bh[3]);
                    mma16816(acc[1][2 * q + 1], ah1, bh[1], bh[3]);
                    if (NPASS == 3) {
                        mma16816(acc[0][2 * q + 1], ah0, bl[1], bl[3]);
                        mma16816(acc[1][2 * q + 1], ah1, bl[1], bl[3]);
                        mma16816(acc[0][2 * q + 1], al0, bh[1], bh[3]);
                        mma16816(acc[1][2 * q + 1], al1, bh[1], bh[3]);
                    }
                }
            }
        }
    };

    if constexpr (NPASS == 1) {
        // ---- deep pipeline: one sync/tap ----
        stageA(0, 0); stageB(0, 0); cpa_commit();
        stageB(1, 1); cpa_commit();
        int t = 0;
#pragma unroll 1
        for (int ky = 0; ky < K; ky++) {
#pragma unroll 1
            for (int kx = 0; kx < K; kx++, t++) {
                if (t + 2 < KK) stageB(t + 2, (t + 2) & 3);
                if (kx == 1 && ky + 1 < K) stageA(ky + 1, (ky + 1) & 1);
                cpa_commit();
                cpa_wait<2>();
                __syncthreads();
                compute_tap(kx, sb + A_OFF + (ky & 1) * ASZ, 0,
                            sb + (t & 3) * BPB, 0);
            }
        }
    } else {
        // ---- conv3 proven path ----
        stageB(0, 0);
        cpa_commit();
        int t = 0;
#pragma unroll 1
        for (int ky = 0; ky < K; ky++) {
            __syncthreads();
            stageA(ky, 0);
            cpa_commit();
#pragma unroll 1
            for (int kx = 0; kx < K; kx++, t++) {
                if (t + 1 < KK) {
                    stageB(t + 1, (t + 1) & 1);
                    cpa_commit();
                    cpa_wait<1>();
                } else {
                    cpa_wait<0>();
                }
                __syncthreads();
                compute_tap(kx, sb + A_OFF, sb + A_OFF + ASZ,
                            sb + (t & 1) * BPB, sb + (t & 1) * BPB + CS * 128);
                __syncthreads();
            }
        }
    }

    const int g = lane >> 2, tg = lane & 3;
    const size_t pixbase = bbase + (size_t)y0 * 256 + xb;
#pragma unroll
    for (int mf = 0; mf < 2; mf++) {
        const int mr = m0 + mf * 16 + g;
#pragma unroll
        for (int nf = 0; nf < NFRAG; nf++) {
            const int col = n0 + nf * 8 + 2 * tg;
            float v00 = acc[mf][nf][0] + bsm[col];
            float v01 = acc[mf][nf][1] + bsm[col + 1];
            float v10 = acc[mf][nf][2] + bsm[col];
            float v11 = acc[mf][nf][3] + bsm[col + 1];
            if (OMODE == 0) {
                float* out = (float*)outv;
                *(float2*)(out + (pixbase + mr) * OSTR + col)     = make_float2(v00, v01);
                *(float2*)(out + (pixbase + mr + 8) * OSTR + col) = make_float2(v10, v11);
                store_h2(obh, (pixbase + mr) * 64 + col, v00, v01);
                store_h2(obh, (pixbase + mr + 8) * 64 + col, v10, v11);
            } else {
                __half* oh = (__half*)outv;
                store_h2(oh, (pixbase + mr) * OSTR + col, v00, v01);
                store_h2(oh, (pixbase + mr + 8) * OSTR + col, v10, v11);
            }
        }
    }
}

// ---------------- p1 1x1 GEMM + exact GELU (fp16, per-batch W) -------------
__global__ void __launch_bounds__(256, 2) k_p1g(
    const __half* __restrict__ Ah, const __half* __restrict__ Wh,
    const float* __restrict__ bias, __half* __restrict__ obh) {
    constexpr int A_OFF = 8192;
    extern __shared__ __align__(128) char smem[];
    uint32_t sb = smem_u32(smem);
    const int tid  = threadIdx.x;
    const int wid  = tid >> 5, lane = tid & 31;
    const int b    = blockIdx.y;
    const int y0   = blockIdx.x >> 1;
    const int xb   = (blockIdx.x & 1) * 128;
    const int m0   = (wid & 3) * 32;
    const int n0   = (wid >> 2) * 32;
    const int lrow = (lane & 7) + (lane & 8);
    const int lc16 = (lane & 16);

    float* bsm = (float*)(smem + A_OFF + 16384);
    if (tid < 64) bsm[tid] = bias[b * 64 + tid];
    {
        const char* sh = (const char*)Wh + (size_t)b * 8192;
        int idx = tid * 16;
        cpa16(sb + idx, sh + idx, 16);
        idx += 4096;
        cpa16(sb + idx, sh + idx, 16);
    }
    const size_t bbase = ((size_t)b << 16);
    const size_t pixbase = bbase + (size_t)y0 * 256 + xb;
    {
        const int r = tid >> 1, halfsel = tid & 1;
        const size_t pb = (pixbase + r) * 128 + (size_t)halfsel * 64;
        const char* sH = (const char*)Ah + pb;
#pragma unroll
        for (int j = 0; j < 4; j++) {
            uint32_t so = swz128((uint32_t)(r * 128 + halfsel * 64 + j * 16));
            cpa16(sb + A_OFF + so, sH + j * 16, 16);
        }
    }
    cpa_commit();
    cpa_wait<0>();
    __syncthreads();

    float acc[2][4][4];
#pragma unroll
    for (int mf = 0; mf < 2; mf++)
#pragma unroll
        for (int nf = 0; nf < 4; nf++)
#pragma unroll
            for (int j = 0; j < 4; j++) acc[mf][nf][j] = 0.f;

#pragma unroll
    for (int kc = 0; kc < 4; kc++) {
        uint32_t ah0[4], ah1[4];
        uint32_t a_off0 = swz128((uint32_t)((m0 + lrow) * 128 + kc * 32 + lc16));
        uint32_t a_off1 = swz128((uint32_t)((m0 + 16 + lrow) * 128 + kc * 32 + lc16));
        ldm4(ah0, sb + A_OFF + a_off0); ldm4(ah1, sb + A_OFF + a_off1);
#pragma unroll
        for (int q = 0; q < 2; q++) {
            uint32_t bh[4];
            uint32_t b_off = swz128((uint32_t)((n0 + 16 * q + lrow) * 128 + kc * 32 + lc16));
            ldm4(bh, sb + b_off);
            mma16816(acc[0][2 * q], ah0, bh[0], bh[2]);
            mma16816(acc[1][2 * q], ah1, bh[0], bh[2]);
            mma16816(acc[0][2 * q + 1], ah0, bh[1], bh[3]);
            mma16816(acc[1][2 * q + 1], ah1, bh[1], bh[3]);
        }
    }

    const int g = lane >> 2, tg = lane & 3;
#pragma unroll
    for (int mf = 0; mf < 2; mf++) {
        const int mr = m0 + mf * 16 + g;
#pragma unroll
        for (int nf = 0; nf < 4; nf++) {
            const int col = n0 + nf * 8 + 2 * tg;
#pragma unroll
            for (int half = 0; half < 2; half++) {
                const size_t pix = pixbase + mr + 8 * half;
                float v0 = gelu_exact(acc[mf][nf][2 * half + 0] + bsm[col]);
                float v1 = gelu_exact(acc[mf][nf][2 * half + 1] + bsm[col + 1]);
                store_h2(obh, pix * 64 + col, v0, v1);
            }
        }
    }
}

// ---------------- fused g1 -> u-mul -> p2 -> shortcut + LeakyReLU ----------
__global__ void __launch_bounds__(256, 2) k_g1p2(
    const __half* __restrict__ Ah, const __half* __restrict__ Uh,
    const __half* __restrict__ Wg, const __half* __restrict__ Wp,
    const float* __restrict__ bg, const float* __restrict__ bp,
    float* __restrict__ dout) {
    constexpr int A_OFF = 16384;
    extern __shared__ __align__(128) char smem[];
    uint32_t sb = smem_u32(smem);
    const int tid  = threadIdx.x;
    const int wid  = tid >> 5, lane = tid & 31;
    const int b    = blockIdx.y;
    const int y0   = blockIdx.x >> 1;
    const int xb   = (blockIdx.x & 1) * 128;
    const int m0   = (wid & 3) * 32;
    const int n0   = (wid >> 2) * 32;
    const int lrow = (lane & 7) + (lane & 8);
    const int lc16 = (lane & 16);

    float* bgs = (float*)(smem + A_OFF + 16384);
    float* bps = bgs + 64;
    float* smn = bgs + 128;
    float* srd = bgs + 192;
    if (tid < 64)       bgs[tid] = bg[tid];
    else if (tid < 128) bps[tid - 64]  = bp[tid - 64];
    else if (tid < 192) smn[tid - 128] = g_stats[b * 64 + tid - 128];
    else if (tid < 256) srd[tid - 192] = g_stats[256 + b * 64 + tid - 192];
    {
        int idx = tid * 16;
        cpa16(sb + idx, (const char*)Wg + idx, 16);
        cpa16(sb + 8192 + idx, (const char*)Wp + idx, 16);
        idx += 4096;
        cpa16(sb + idx, (const char*)Wg + idx, 16);
        cpa16(sb + 8192 + idx, (const char*)Wp + idx, 16);
    }
    const size_t bbase = ((size_t)b << 16);
    const size_t pixbase = bbase + (size_t)y0 * 256 + xb;
    {
        const int r = tid >> 1, halfsel = tid & 1;
        const size_t pb = (pixbase + r) * 128 + (size_t)halfsel * 64;
        const char* sH = (const char*)Ah + pb;
#pragma unroll
        for (int j = 0; j < 4; j++) {
            uint32_t so = swz128((uint32_t)(r * 128 + halfsel * 64 + j * 16));
            cpa16(sb + A_OFF + so, sH + j * 16, 16);
        }
    }
    cpa_commit();
    cpa_wait<0>();
    __syncthreads();

    float acc[2][4][4];
#pragma unroll
    for (int mf = 0; mf < 2; mf++)
#pragma unroll
        for (int nf = 0; nf < 4; nf++)
#pragma unroll
            for (int j = 0; j < 4; j++) acc[mf][nf][j] = 0.f;

    // ---- GEMM 1: v = a2 * Wg ----
#pragma unroll
    for (int kc = 0; kc < 4; kc++) {
        uint32_t ah0[4], ah1[4];
        uint32_t a_off0 = swz128((uint32_t)((m0 + lrow) * 128 + kc * 32 + lc16));
        uint32_t a_off1 = swz128((uint32_t)((m0 + 16 + lrow) * 128 + kc * 32 + lc16));
        ldm4(ah0, sb + A_OFF + a_off0); ldm4(ah1, sb + A_OFF + a_off1);
#pragma unroll
        for (int q = 0; q < 2; q++) {
            uint32_t bh[4];
            uint32_t b_off = swz128((uint32_t)((n0 + 16 * q + lrow) * 128 + kc * 32 + lc16));
            ldm4(bh, sb + b_off);
            mma16816(acc[0][2 * q], ah0, bh[0], bh[2]);
            mma16816(acc[1][2 * q], ah1, bh[0], bh[2]);
            mma16816(acc[0][2 * q + 1], ah0, bh[1], bh[3]);
            mma16816(acc[1][2 * q + 1], ah1, bh[1], bh[3]);
        }
    }
    __syncthreads();

    // ---- epilogue 1: t = u * (v + bg), store fp16 to A smem ----
    const int g = lane >> 2, tg = lane & 3;
#pragma unroll
    for (int mf = 0; mf < 2; mf++) {
        const int mr = m0 + mf * 16 + g;
#pragma unroll
        for (int nf = 0; nf < 4; nf++) {
            const int col = n0 + nf * 8 + 2 * tg;
#pragma unroll
            for (int half = 0; half < 2; half++) {
                const int r = mr + 8 * half;
                const size_t pix = pixbase + r;
                float v0 = acc[mf][nf][2 * half + 0] + bgs[col];
                float v1 = acc[mf][nf][2 * half + 1] + bgs[col + 1];
                float2 u = __half22float2(*(const __half2*)(Uh + pix * 64 + col));
                uint32_t so = swz128((uint32_t)(r * 128 + col * 2));
                *(__half2*)(smem + A_OFF + so) = __floats2half2_rn(v0 * u.x, v1 * u.y);
            }
        }
    }
    __syncthreads();

    // ---- GEMM 2: p2(t) ----
#pragma unroll
    for (int mf = 0; mf < 2; mf++)
#pragma unroll
        for (int nf = 0; nf < 4; nf++)
#pragma unroll
            for (int j = 0; j < 4; j++) acc[mf][nf][j] = 0.f;
#pragma unroll
    for (int kc = 0; kc < 4; kc++) {
        uint32_t ah0[4], ah1[4];
        uint32_t a_off0 = swz128((uint32_t)((m0 + lrow) * 128 + kc * 32 + lc16));
        uint32_t a_off1 = swz128((uint32_t)((m0 + 16 + lrow) * 128 + kc * 32 + lc16));
        ldm4(ah0, sb + A_OFF + a_off0); ldm4(ah1, sb + A_OFF + a_off1);
#pragma unroll
        for (int q = 0; q < 2; q++) {
            uint32_t bh[4];
            uint32_t b_off = swz128((uint32_t)(8192 + (n0 + 16 * q + lrow) * 128 + kc * 32 + lc16));
            ldm4(bh, sb + b_off);
            mma16816(acc[0][2 * q], ah0, bh[0], bh[2]);
            mma16816(acc[1][2 * q], ah1, bh[0], bh[2]);
            mma16816(acc[0][2 * q + 1], ah0, bh[1], bh[3]);
            mma16816(acc[1][2 * q + 1], ah1, bh[1], bh[3]);
        }
    }

    // ---- epilogue 2: + bias + normalized shortcut, LeakyReLU, NCHW ----
#pragma unroll
    for (int mf = 0; mf < 2; mf++) {
        const int mr = m0 + mf * 16 + g;
#pragma unroll
        for (int nf = 0; nf < 4; nf++) {
            const int col = n0 + nf * 8 + 2 * tg;
#pragma unroll
            for (int half = 0; half < 2; half++) {
                const size_t pix = pixbase + mr + 8 * half;
                float v0 = acc[mf][nf][2 * half + 0] + bps[col];
                float v1 = acc[mf][nf][2 * half + 1] + bps[col + 1];
                float2 hh = *(const float2*)(&g_h[pix * 64 + col]);
                v0 += (hh.x - smn[col])     * srd[col];
                v1 += (hh.y - smn[col + 1]) * srd[col + 1];
                v0 = (v0 >= 0.f) ? v0 : 0.2f * v0;
                v1 = (v1 >= 0.f) ? v1 : 0.2f * v1;
                const size_t ppix = pix - bbase;
                dout[(((size_t)(b * 64 + col))     << 16) + ppix] = v0;
                dout[(((size_t)(b * 64 + col + 1)) << 16) + ppix] = v1;
            }
        }
    }
}

// ---------------- instance-norm statistics ---------------------------------
__global__ void k_stats_part() {
    int b = blockIdx.y, s = blockIdx.x;
    int tid = threadIdx.x;
    int c = tid & 63, g = tid >> 6;
    float su = 0.f, sq = 0.f;
    const float* base = g_h + ((size_t)b * PIX + (size_t)s * 2048) * 64;
    for (int p = g; p < 2048; p += 4) {
        float v = base[(size_t)p * 64 + c];
        su += v; sq += v * v;
    }
    __shared__ float bu[256], bq[256];
    bu[tid] = su; bq[tid] = sq;
    __syncthreads();
    if (g == 0) {
        su = bu[c] + bu[64 + c] + bu[128 + c] + bu[192 + c];
        sq = bq[c] + bq[64 + c] + bq[128 + c] + bq[192 + c];
        g_part[((b * 32 + s) * 64 + c) * 2 + 0] = su;
        g_part[((b * 32 + s) * 64 + c) * 2 + 1] = sq;
    }
}
__global__ void k_stats_final() {
    int tid = threadIdx.x;
    int b = tid >> 6, c = tid & 63;
    float su = 0.f, sq = 0.f;
    for (int s = 0; s < 32; s++) {
        su += g_part[((b * 32 + s) * 64 + c) * 2 + 0];
        sq += g_part[((b * 32 + s) * 64 + c) * 2 + 1];
    }
    float m   = su * (1.f / 65536.f);
    float var = sq * (1.f / 65536.f) - m * m;
    g_stats[tid]       = m;
    g_stats[256 + tid] = rsqrtf(var + 1e-5f);
}

// ---------------- deformable depthwise conv (fp16 gather, 8 thr/px) --------
template <int K, int OSTR, int PAD, int DIL>
__global__ void __launch_bounds__(256) k_deform(const __half* __restrict__ in,
                                                const __half* __restrict__ off,
                                                const float* __restrict__ dw,
                                                __half* __restrict__ obh) {
    constexpr int KK = K * K;
    __shared__ __align__(16) float ws[KK * 64];
    int tid = threadIdx.x;
    for (int i = tid; i < KK * 64; i += 256) {
        int k = i >> 6, c = i & 63;
        ws[i] = dw[c * KK + k];
    }
    __syncthreads();
    int gp = blockIdx.x * 32 + (tid >> 3);
    int c0 = (tid & 7) * 8;
    int b = gp >> 16, p = gp & 65535;
    int y = p >> 8, x = p & 255;
    const __half* offp = off + (size_t)gp * OSTR;
    const __half* inb = in + (((size_t)b) << 16) * 64;
    float a[8] = {0.f, 0.f, 0.f, 0.f, 0.f, 0.f, 0.f, 0.f};
#pragma unroll 1
    for (int k = 0; k < KK; k++) {
        float2 o2 = __half22float2(*(const __half2*)(offp + 2 * k));
        float py = (float)(y - PAD + DIL * (k / K)) + o2.x;
        float px = (float)(x - PAD + DIL * (k % K)) + o2.y;
        float y0f = floorf(py), x0f = floorf(px);
        float fy = py - y0f, fx = px - x0f;
        int y0 = (int)y0f, x0 = (int)x0f;
        bool yv0 = (y0 >= 0) & (y0 <= 255);
        bool yv1 = (y0 >= -1) & (y0 <= 254);
        bool xv0 = (x0 >= 0) & (x0 <= 255);
        bool xv1 = (x0 >= -1) & (x0 <= 254);
        float w00 = (1.f - fy) * (1.f - fx), w01 = (1.f - fy) * fx;
        float w10 = fy * (1.f - fx),         w11 = fy * fx;
        float s[8] = {0.f, 0.f, 0.f, 0.f, 0.f, 0.f, 0.f, 0.f};
        auto addc = [&](int yy, int xx, float wgt) {
            uint4 v = *(const uint4*)(inb + ((size_t)(yy * 256 + xx)) * 64 + c0);
            const __half2* hp = (const __half2*)&v;
#pragma unroll
            for (int j = 0; j < 4; j++) {
                float2 f = __half22float2(hp[j]);
                s[2 * j]     += f.x * wgt;
                s[2 * j + 1] += f.y * wgt;
            }
        };
        if (yv0) {
            if (xv0) addc(y0, x0, w00);
            if (xv1) addc(y0, x0 + 1, w01);
        }
        if (yv1) {
            if (xv0) addc(y0 + 1, x0, w10);
            if (xv1) addc(y0 + 1, x0 + 1, w11);
        }
        float4 wk0 = *(const float4*)(ws + k * 64 + c0);
        float4 wk1 = *(const float4*)(ws + k * 64 + c0 + 4);
        a[0] = fmaf(s[0], wk0.x, a[0]);
        a[1] = fmaf(s[1], wk0.y, a[1]);
        a[2] = fmaf(s[2], wk0.z, a[2]);
        a[3] = fmaf(s[3], wk0.w, a[3]);
        a[4] = fmaf(s[4], wk1.x, a[4]);
        a[5] = fmaf(s[5], wk1.y, a[5]);
        a[6] = fmaf(s[6], wk1.z, a[6]);
        a[7] = fmaf(s[7], wk1.w, a[7]);
    }
    __half2 r[4];
#pragma unroll
    for (int j = 0; j < 4; j++) r[j] = __floats2half2_rn(a[2 * j], a[2 * j + 1]);
    *(uint4*)(obh + (size_t)gp * 64 + c0) = *(uint4*)r;
}

// ---------------------------------------------------------------------------
extern "C" void kernel_launch(void* const* d_in, const int* in_sizes, int n_in,
                              void* d_out, int out_size) {
    const float* x      = (const float*)d_in[0];
    const float* conv_w = (const float*)d_in[1];
    const float* p1_w   = (const float*)d_in[2];
    const float* p1_b   = (const float*)d_in[3];
    const float* off0_w = (const float*)d_in[4];
    const float* off0_b = (const float*)d_in[5];
    const float* dw0_w  = (const float*)d_in[6];
    const float* offs_w = (const float*)d_in[7];
    const float* offs_b = (const float*)d_in[8];
    const float* dws_w  = (const float*)d_in[9];
    const float* g1_w   = (const float*)d_in[10];
    const float* g1_b   = (const float*)d_in[11];
    const float* p2_w   = (const float*)d_in[12];
    const float* p2_b   = (const float*)d_in[13];
    float* out = (float*)d_out;

    float *h, *bp1;
    __half *offb, *bfh, *bfl, *b2h;
    __half *w3h, *w3l, *w5h, *w7h, *wp1h, *wg1h, *wp2h;
    cudaGetSymbolAddress((void**)&h,    g_h);
    cudaGetSymbolAddress((void**)&offb, g_off);
    cudaGetSymbolAddress((void**)&bp1,  g_bp1);
    cudaGetSymbolAddress((void**)&bfh,  g_bfh);
    cudaGetSymbolAddress((void**)&bfl,  g_bfl);
    cudaGetSymbolAddress((void**)&b2h,  g_b2h);
    cudaGetSymbolAddress((void**)&w3h,  g_w3h);
    cudaGetSymbolAddress((void**)&w3l,  g_w3l);
    cudaGetSymbolAddress((void**)&w5h,  g_w5h);
    cudaGetSymbolAddress((void**)&w7h,  g_w7h);
    cudaGetSymbolAddress((void**)&wp1h, g_wp1h);
    cudaGetSymbolAddress((void**)&wg1h, g_wg1h);
    cudaGetSymbolAddress((void**)&wp2h, g_wp2h);

    const int SM_3 = 2 * 16384 + 2 * 17408 + 512;   // 68352 (2-buf, hi/lo)
    const int SM_5 = 4 * 8192  + 2 * 17408 + 512;   // 68096 (4-buf B, 2-buf A)
    const int SM_7 = 4 * 14336 + 2 * 19456 + 512;   // 96768
    const int SM_P = 8192 + 16384 + 1024;           // 25600
    const int SM_F = 16384 + 16384 + 1024;          // 33792
    cudaFuncSetAttribute((const void*)k_mmaconv<64, 64, 4, 3, 1, 1, false, 64, 3, 0>,
                         cudaFuncAttributeMaxDynamicSharedMemorySize, SM_3);
    cudaFuncSetAttribute((const void*)k_mmaconv<50, 64, 4, 5, 2, 1, true, 64, 1, 1>,
                         cudaFuncAttributeMaxDynamicSharedMemorySize, SM_5);
    cudaFuncSetAttribute((const void*)k_mmaconv<98, 112, 7, 7, 9, 3, true, 112, 1, 1>,
                         cudaFuncAttributeMaxDynamicSharedMemorySize, SM_7);
    cudaFuncSetAttribute((const void*)k_p1g,
                         cudaFuncAttributeMaxDynamicSharedMemorySize, SM_P);
    cudaFuncSetAttribute((const void*)k_g1p2,
                         cudaFuncAttributeMaxDynamicSharedMemorySize, SM_F);

    k_x2bf<<<dim3(PIX / 32, CH / 32, BB), dim3(32, 8)>>>(x);
    k_prepw<<<(9  * 64  * 64 + 255) / 256, 256>>>(conv_w, w3h, w3l, 64, 64, 9);
    k_prepw<<<(25 * 64  * 64 + 255) / 256, 256>>>(off0_w, w5h, nullptr, 50, 64, 25);
    k_prepw<<<(49 * 112 * 64 + 255) / 256, 256>>>(offs_w, w7h, nullptr, 98, 112, 49);
    k_prepw<<<16, 256>>>(g1_w, wg1h, nullptr, 64, 64, 1);
    k_prepw<<<16, 256>>>(p2_w, wp2h, nullptr, 64, 64, 1);

    dim3 mg(IH * 2, BB);

    // conv3 (3-pass): x hi/lo -> g_h fp32 + h-hi (b2h)
    k_mmaconv<64, 64, 4, 3, 1, 1, false, 64, 3, 0>
        <<<mg, 256, SM_3>>>(bfh, bfl, w3h, w3l, nullptr, (void*)h, b2h);
    k_stats_part<<<dim3(32, BB), 256>>>();
    k_stats_final<<<1, 256>>>();
    k_prepp1<<<256, 64>>>(p1_w, p1_b);

    // p1 + gelu: h-hi -> u-hi (bfh; x dead)
    k_p1g<<<mg, 256, SM_P>>>(b2h, wp1h, bp1, bfh);

    // conv5 offsets (fp16 out): u-hi -> g_off
    k_mmaconv<50, 64, 4, 5, 2, 1, true, 64, 1, 1>
        <<<mg, 256, SM_5>>>(bfh, nullptr, w5h, nullptr, off0_b, (void*)offb, nullptr);
    // deform5: sample u-hi -> a1-hi (b2h; h-hi dead)
    k_deform<5, 64, 2, 1><<<NPIX / 32, 256>>>(bfh, offb, dw0_w, b2h);

    // conv7 offsets (fp16 out): a1-hi -> g_off
    k_mmaconv<98, 112, 7, 7, 9, 3, true, 112, 1, 1>
        <<<mg, 256, SM_7>>>(b2h, nullptr, w7h, nullptr, offs_b, (void*)offb, nullptr);
    // deform7: sample a1-hi -> a2-hi (bfl; x-lo dead)
    k_deform<7, 112, 9, 3><<<NPIX / 32, 256>>>(b2h, offb, dws_w, bfl);

    // fused g1 -> u-mul -> p2 -> shortcut + LeakyReLU -> NCHW
    k_g1p2<<<mg, 256, SM_F>>>(bfl, bfh, wg1h, wp2h, g1_b, p2_b, out);
}

// round 13
// speedup vs baseline: 1.2164x; 1.2164x over previous
#include <cuda_runtime.h>
#include <cuda_fp16.h>
#include <cstdint>

// ---------------------------------------------------------------------------
// DLKA conv block. R9 structure (best: 1761us) + half2-SIMD deform inner loop
// + epilogue store guard for padded conv outputs.
// ---------------------------------------------------------------------------

static constexpr int BB   = 4;
static constexpr int CH   = 64;
static constexpr int IH   = 256;
static constexpr int IW   = 256;
static constexpr int PIX  = IH * IW;
static constexpr int NPIX = BB * PIX;

// ----------------------------- device scratch ------------------------------
__device__ float g_h  [(size_t)NPIX * CH];    // conv3 raw out (fp32, shortcut)
__device__ __half g_off[(size_t)NPIX * 112];  // offset maps (fp16)
__device__ __half g_bfh[(size_t)NPIX * CH], g_bfl[(size_t)NPIX * CH];
__device__ __half g_b2h[(size_t)NPIX * CH];
__device__ __half g_w3h[9  * 64  * 64], g_w3l[9 * 64 * 64];
__device__ __half g_w5h[25 * 64  * 64];
__device__ __half g_w7h[49 * 112 * 64];
__device__ __half g_wp1h[4 * 64 * 64];
__device__ __half g_wg1h[64 * 64];
__device__ __half g_wp2h[64 * 64];
__device__ float g_bp1[256];
__device__ float g_part[BB * 32 * 64 * 2];
__device__ float g_stats[512];

// ----------------------------- helpers -------------------------------------
__device__ __forceinline__ uint32_t smem_u32(const void* p) {
    uint32_t a;
    asm("{ .reg .u64 t; cvta.to.shared.u64 t, %1; cvt.u32.u64 %0, t; }"
        : "=r"(a) : "l"(p));
    return a;
}
__device__ __host__ __forceinline__ uint32_t swz128(uint32_t off) {
    return off ^ ((off >> 3) & 0x70);
}
__device__ __forceinline__ void ldm4(uint32_t* r, uint32_t addr) {
    asm volatile("ldmatrix.sync.aligned.m8n8.x4.shared.b16 {%0,%1,%2,%3}, [%4];"
                 : "=r"(r[0]), "=r"(r[1]), "=r"(r[2]), "=r"(r[3]) : "r"(addr));
}
__device__ __forceinline__ void mma16816(float* c, const uint32_t* a,
                                         uint32_t b0, uint32_t b1) {
    asm volatile(
        "mma.sync.aligned.m16n8k16.row.col.f32.f16.f16.f32 "
        "{%0,%1,%2,%3}, {%4,%5,%6,%7}, {%8,%9}, {%0,%1,%2,%3};"
        : "+f"(c[0]), "+f"(c[1]), "+f"(c[2]), "+f"(c[3])
        : "r"(a[0]), "r"(a[1]), "r"(a[2]), "r"(a[3]), "r"(b0), "r"(b1));
}
__device__ __forceinline__ void cpa16(uint32_t dst, const void* src, int sz) {
    asm volatile("cp.async.cg.shared.global [%0], [%1], 16, %2;"
                 :: "r"(dst), "l"(src), "r"(sz) : "memory");
}
__device__ __forceinline__ void cpa_commit() {
    asm volatile("cp.async.commit_group;" ::: "memory");
}
template <int N>
__device__ __forceinline__ void cpa_wait() {
    asm volatile("cp.async.wait_group %0;" :: "n"(N) : "memory");
}
__device__ __forceinline__ float gelu_exact(float v) {
    return 0.5f * v * (1.f + erff(v * 0.70710678118654752440f));
}
__device__ __forceinline__ void store_h2(__half* p, size_t idx, float v0, float v1) {
    *(__half2*)(p + idx) = __floats2half2_rn(v0, v1);
}

// ---------------- NCHW -> NHWC transpose to fp16 hi/lo ---------------------
__global__ void k_x2bf(const float* __restrict__ in) {
    __shared__ float tile[32][33];
    int b = blockIdx.z, p0 = blockIdx.x * 32, c0 = blockIdx.y * 32;
    int tx = threadIdx.x, ty = threadIdx.y;
#pragma unroll
    for (int i = 0; i < 4; i++)
        tile[ty + 8 * i][tx] =
            in[((size_t)(b * CH + c0 + ty + 8 * i)) * PIX + p0 + tx];
    __syncthreads();
#pragma unroll
    for (int i = 0; i < 4; i++) {
        float v = tile[tx][ty + 8 * i];
        size_t ix = ((size_t)b * PIX + p0 + ty + 8 * i) * CH + c0 + tx;
        __half h = __float2half_rn(v);
        g_bfh[ix] = h;
        g_bfl[ix] = __float2half_rn(v - __half2float(h));
    }
}

// ------- weight prep: [o][c][kh][kw] -> pre-swizzled fp16 [tap][o][c] ------
__global__ void k_prepw(const float* __restrict__ w, __half* __restrict__ wh,
                        __half* __restrict__ wl, int COUT, int CS, int KK) {
    int idx = blockIdx.x * 256 + threadIdx.x;
    int total = KK * CS * 64;
    if (idx >= total) return;
    int tap = idx / (CS * 64);
    int r = idx - tap * CS * 64;
    int o = r >> 6, c = r & 63;
    float v = (o < COUT) ? w[((size_t)o * 64 + c) * KK + tap] : 0.f;
    __half h = __float2half_rn(v);
    uint32_t so = swz128((uint32_t)(o * 128 + c * 2));
    size_t base = (size_t)tap * CS * 128;
    *(__half*)((char*)wh + base + so) = h;
    if (wl)
        *(__half*)((char*)wl + base + so) = __float2half_rn(v - __half2float(h));
}

// ------- p1 weight fold: w'[b,o,c] = w[o,c]*rstd[b,c]; bias fold -----------
__global__ void k_prepp1(const float* __restrict__ w, const float* __restrict__ bias) {
    int b = blockIdx.x >> 6, o = blockIdx.x & 63;
    int c = threadIdx.x;
    float r = g_stats[256 + b * 64 + c];
    float m = g_stats[b * 64 + c];
    float wv = w[o * 64 + c] * r;
    uint32_t so = swz128((uint32_t)(o * 128 + c * 2));
    *(__half*)((char*)g_wp1h + (size_t)b * 64 * 128 + so) = __float2half_rn(wv);
    __shared__ float red[64];
    red[c] = wv * m;
    __syncthreads();
    if (c < 32) red[c] += red[c + 32];
    __syncwarp();
    if (c < 16) red[c] += red[c + 16];
    __syncwarp();
    if (c < 8)  red[c] += red[c + 8];
    __syncwarp();
    if (c < 4)  red[c] += red[c + 4];
    __syncwarp();
    if (c == 0)
        g_bp1[b * 64 + o] = bias[o] - (red[0] + red[1] + red[2] + red[3]);
}

// ---------------- mma.sync conv with cp.async pipeline (R9 proven) ---------
template <int COUT, int CS, int NFRAG, int K, int PAD, int DIL, bool HASB,
          int OSTR, int NPASS, int OMODE>
__global__ void __launch_bounds__(256, 2) k_mmaconv(
    const __half* __restrict__ Ah, const __half* __restrict__ Al,
    const __half* __restrict__ Wh, const __half* __restrict__ Wl,
    const float* __restrict__ bias, void* __restrict__ outv,
    __half* __restrict__ obh) {
    constexpr int KK   = K * K;
    constexpr int NQ   = (NFRAG + 1) / 2;
    constexpr int WPX  = 128 + (K - 1) * DIL;
    constexpr int ASZ  = ((WPX * 128 + 1023) / 1024) * 1024;
    constexpr int BPB  = CS * 128 * (NPASS == 3 ? 2 : 1);
    constexpr int A_OFF = 2 * BPB;
    constexpr int BIAS_OFF = A_OFF + ASZ * (NPASS == 3 ? 2 : 1);
    extern __shared__ __align__(128) char smem[];
    uint32_t sb = smem_u32(smem);
    const int tid  = threadIdx.x;
    const int wid  = tid >> 5, lane = tid & 31;
    const int b    = blockIdx.y;
    const int y0   = blockIdx.x >> 1;
    const int xb   = (blockIdx.x & 1) * 128;
    const int m0   = (wid & 3) * 32;
    const int n0   = (wid >> 2) * (NFRAG * 8);
    const int lrow = (lane & 7) + (lane & 8);
    const int lc16 = (lane & 16);
    const size_t bbase = ((size_t)b << 16);

    float* bsm = (float*)(smem + BIAS_OFF);
    for (int i = tid; i < OSTR; i += 256)
        bsm[i] = (HASB && i < COUT) ? bias[i] : 0.f;

    float acc[2][NFRAG][4];
#pragma unroll
    for (int mf = 0; mf < 2; mf++)
#pragma unroll
        for (int nf = 0; nf < NFRAG; nf++)
#pragma unroll
            for (int j = 0; j < 4; j++) acc[mf][nf][j] = 0.f;

    auto stageB = [&](int tap, int buf) {
        const char* sh = (const char*)Wh + (size_t)tap * CS * 128;
        uint32_t d = sb + buf * BPB;
        for (int idx = tid * 16; idx < CS * 128; idx += 256 * 16) {
            cpa16(d + idx, sh + idx, 16);
            if (NPASS == 3)
                cpa16(d + CS * 128 + idx,
                      (const char*)Wl + (size_t)tap * CS * 128 + idx, 16);
        }
    };
    auto stageA = [&](int ky) {
        const int ysrc = y0 + ky * DIL - PAD;
        const bool yok = (unsigned)ysrc < 256u;
        const size_t rowb = (bbase + (size_t)ysrc * 256) * 128;
        for (int i = tid; i < WPX * 8; i += 256) {
            int p = i >> 3, u = i & 7;
            int xs = xb - PAD + p;
            bool ok = yok && ((unsigned)xs < 256u);
            size_t off = ok ? rowb + (size_t)xs * 128 + u * 16 : 0;
            int sz = ok ? 16 : 0;
            uint32_t d = swz128((uint32_t)(p * 128 + u * 16));
            cpa16(sb + A_OFF + d, (const char*)Ah + off, sz);
            if (NPASS == 3)
                cpa16(sb + A_OFF + ASZ + d, (const char*)Al + off, sz);
        }
    };

    stageB(0, 0);
    cpa_commit();

    int t = 0;
#pragma unroll 1
    for (int ky = 0; ky < K; ky++) {
        __syncthreads();
        stageA(ky);
        cpa_commit();
#pragma unroll 1
        for (int kx = 0; kx < K; kx++, t++) {
            if (t + 1 < KK) {
                stageB(t + 1, (t + 1) & 1);
                cpa_commit();
                cpa_wait<1>();
            } else {
                cpa_wait<0>();
            }
            __syncthreads();
            const int kxo = kx * DIL;
            const uint32_t AbH = sb + A_OFF, AbL = sb + A_OFF + ASZ;
            const uint32_t BbH = sb + (t & 1) * BPB, BbL = BbH + CS * 128;
#pragma unroll
            for (int kc = 0; kc < 4; kc++) {
                uint32_t ah0[4], ah1[4], al0[4], al1[4];
                uint32_t a_off0 = swz128((uint32_t)((kxo + m0 + lrow) * 128 + kc * 32 + lc16));
                uint32_t a_off1 = swz128((uint32_t)((kxo + m0 + 16 + lrow) * 128 + kc * 32 + lc16));
                ldm4(ah0, AbH + a_off0); ldm4(ah1, AbH + a_off1);
                if (NPASS == 3) { ldm4(al0, AbL + a_off0); ldm4(al1, AbL + a_off1); }
#pragma unroll
                for (int q = 0; q < NQ; q++) {
                    uint32_t bh[4], bl[4];
                    uint32_t b_off = swz128((uint32_t)((n0 + 16 * q + lrow) * 128 + kc * 32 + lc16));
                    ldm4(bh, BbH + b_off);
                    if (NPASS == 3) ldm4(bl, BbL + b_off);
                    mma16816(acc[0][2 * q], ah0, bh[0], bh[2]);
                    mma16816(acc[1][2 * q], ah1, bh[0], bh[2]);
                    if (NPASS == 3) {
                        mma16816(acc[0][2 * q], ah0, bl[0], bl[2]);
                        mma16816(acc[1][2 * q], ah1, bl[0], bl[2]);
                        mma16816(acc[0][2 * q], al0, bh[0], bh[2]);
                        mma16816(acc[1][2 * q], al1, bh[0], bh[2]);
                    }
                    if (2 * q + 1 < NFRAG) {
                        mma16816(acc[0][2 * q + 1], ah0, bh[1], bh[3]);
                        mma16816(acc[1][2 * q + 1], ah1, bh[1], bh[3]);
                        if (NPASS == 3) {
                            mma16816(acc[0][2 * q + 1], ah0, bl[1], bl[3]);
                            mma16816(acc[1][2 * q + 1], ah1, bl[1], bl[3]);
                            mma16816(acc[0][2 * q + 1], al0, bh[1], bh[3]);
                            mma16816(acc[1][2 * q + 1], al1, bh[1], bh[3]);
                        }
                    }
                }
            }
            __syncthreads();
        }
    }

    const int g = lane >> 2, tg = lane & 3;
    const size_t pixbase = bbase + (size_t)y0 * 256 + xb;
#pragma unroll
    for (int mf = 0; mf < 2; mf++) {
        const int mr = m0 + mf * 16 + g;
#pragma unroll
        for (int nf = 0; nf < NFRAG; nf++) {
            const int col = n0 + nf * 8 + 2 * tg;
            float v00 = acc[mf][nf][0] + bsm[col];
            float v01 = acc[mf][nf][1] + bsm[col + 1];
            float v10 = acc[mf][nf][2] + bsm[col];
            float v11 = acc[mf][nf][3] + bsm[col + 1];
            if (OMODE == 0) {
                float* out = (float*)outv;
                *(float2*)(out + (pixbase + mr) * OSTR + col)     = make_float2(v00, v01);
                *(float2*)(out + (pixbase + mr + 8) * OSTR + col) = make_float2(v10, v11);
                store_h2(obh, (pixbase + mr) * 64 + col, v00, v01);
                store_h2(obh, (pixbase + mr + 8) * 64 + col, v10, v11);
            } else {
                if (col < COUT) {     // skip padded output columns
                    __half* oh = (__half*)outv;
                    store_h2(oh, (pixbase + mr) * OSTR + col, v00, v01);
                    store_h2(oh, (pixbase + mr + 8) * OSTR + col, v10, v11);
                }
            }
        }
    }
}

// ---------------- p1 1x1 GEMM + exact GELU (fp16, per-batch W) -------------
__global__ void __launch_bounds__(256, 2) k_p1g(
    const __half* __restrict__ Ah, const __half* __restrict__ Wh,
    const float* __restrict__ bias, __half* __restrict__ obh) {
    constexpr int A_OFF = 8192;
    extern __shared__ __align__(128) char smem[];
    uint32_t sb = smem_u32(smem);
    const int tid  = threadIdx.x;
    const int wid  = tid >> 5, lane = tid & 31;
    const int b    = blockIdx.y;
    const int y0   = blockIdx.x >> 1;
    const int xb   = (blockIdx.x & 1) * 128;
    const int m0   = (wid & 3) * 32;
    const int n0   = (wid >> 2) * 32;
    const int lrow = (lane & 7) + (lane & 8);
    const int lc16 = (lane & 16);

    float* bsm = (float*)(smem + A_OFF + 16384);
    if (tid < 64) bsm[tid] = bias[b * 64 + tid];
    {
        const char* sh = (const char*)Wh + (size_t)b * 8192;
        int idx = tid * 16;
        cpa16(sb + idx, sh + idx, 16);
        idx += 4096;
        cpa16(sb + idx, sh + idx, 16);
    }
    const size_t bbase = ((size_t)b << 16);
    const size_t pixbase = bbase + (size_t)y0 * 256 + xb;
    {
        const int r = tid >> 1, halfsel = tid & 1;
        const size_t pb = (pixbase + r) * 128 + (size_t)halfsel * 64;
        const char* sH = (const char*)Ah + pb;
#pragma unroll
        for (int j = 0; j < 4; j++) {
            uint32_t so = swz128((uint32_t)(r * 128 + halfsel * 64 + j * 16));
            cpa16(sb + A_OFF + so, sH + j * 16, 16);
        }
    }
    cpa_commit();
    cpa_wait<0>();
    __syncthreads();

    float acc[2][4][4];
#pragma unroll
    for (int mf = 0; mf < 2; mf++)
#pragma unroll
        for (int nf = 0; nf < 4; nf++)
#pragma unroll
            for (int j = 0; j < 4; j++) acc[mf][nf][j] = 0.f;

#pragma unroll
    for (int kc = 0; kc < 4; kc++) {
        uint32_t ah0[4], ah1[4];
        uint32_t a_off0 = swz128((uint32_t)((m0 + lrow) * 128 + kc * 32 + lc16));
        uint32_t a_off1 = swz128((uint32_t)((m0 + 16 + lrow) * 128 + kc * 32 + lc16));
        ldm4(ah0, sb + A_OFF + a_off0); ldm4(ah1, sb + A_OFF + a_off1);
#pragma unroll
        for (int q = 0; q < 2; q++) {
            uint32_t bh[4];
            uint32_t b_off = swz128((uint32_t)((n0 + 16 * q + lrow) * 128 + kc * 32 + lc16));
            ldm4(bh, sb + b_off);
            mma16816(acc[0][2 * q], ah0, bh[0], bh[2]);
            mma16816(acc[1][2 * q], ah1, bh[0], bh[2]);
            mma16816(acc[0][2 * q + 1], ah0, bh[1], bh[3]);
            mma16816(acc[1][2 * q + 1], ah1, bh[1], bh[3]);
        }
    }

    const int g = lane >> 2, tg = lane & 3;
#pragma unroll
    for (int mf = 0; mf < 2; mf++) {
        const int mr = m0 + mf * 16 + g;
#pragma unroll
        for (int nf = 0; nf < 4; nf++) {
            const int col = n0 + nf * 8 + 2 * tg;
#pragma unroll
            for (int half = 0; half < 2; half++) {
                const size_t pix = pixbase + mr + 8 * half;
                float v0 = gelu_exact(acc[mf][nf][2 * half + 0] + bsm[col]);
                float v1 = gelu_exact(acc[mf][nf][2 * half + 1] + bsm[col + 1]);
                store_h2(obh, pix * 64 + col, v0, v1);
            }
        }
    }
}

// ---------------- fused g1 -> u-mul -> p2 -> shortcut + LeakyReLU ----------
__global__ void __launch_bounds__(256, 2) k_g1p2(
    const __half* __restrict__ Ah, const __half* __restrict__ Uh,
    const __half* __restrict__ Wg, const __half* __restrict__ Wp,
    const float* __restrict__ bg, const float* __restrict__ bp,
    float* __restrict__ dout) {
    constexpr int A_OFF = 16384;
    extern __shared__ __align__(128) char smem[];
    uint32_t sb = smem_u32(smem);
    const int tid  = threadIdx.x;
    const int wid  = tid >> 5, lane = tid & 31;
    const int b    = blockIdx.y;
    const int y0   = blockIdx.x >> 1;
    const int xb   = (blockIdx.x & 1) * 128;
    const int m0   = (wid & 3) * 32;
    const int n0   = (wid >> 2) * 32;
    const int lrow = (lane & 7) + (lane & 8);
    const int lc16 = (lane & 16);

    float* bgs = (float*)(smem + A_OFF + 16384);
    float* bps = bgs + 64;
    float* smn = bgs + 128;
    float* srd = bgs + 192;
    if (tid < 64)       bgs[tid] = bg[tid];
    else if (tid < 128) bps[tid - 64]  = bp[tid - 64];
    else if (tid < 192) smn[tid - 128] = g_stats[b * 64 + tid - 128];
    else if (tid < 256) srd[tid - 192] = g_stats[256 + b * 64 + tid - 192];
    {
        int idx = tid * 16;
        cpa16(sb + idx, (const char*)Wg + idx, 16);
        cpa16(sb + 8192 + idx, (const char*)Wp + idx, 16);
        idx += 4096;
        cpa16(sb + idx, (const char*)Wg + idx, 16);
        cpa16(sb + 8192 + idx, (const char*)Wp + idx, 16);
    }
    const size_t bbase = ((size_t)b << 16);
    const size_t pixbase = bbase + (size_t)y0 * 256 + xb;
    {
        const int r = tid >> 1, halfsel = tid & 1;
        const size_t pb = (pixbase + r) * 128 + (size_t)halfsel * 64;
        const char* sH = (const char*)Ah + pb;
#pragma unroll
        for (int j = 0; j < 4; j++) {
            uint32_t so = swz128((uint32_t)(r * 128 + halfsel * 64 + j * 16));
            cpa16(sb + A_OFF + so, sH + j * 16, 16);
        }
    }
    cpa_commit();
    cpa_wait<0>();
    __syncthreads();

    float acc[2][4][4];
#pragma unroll
    for (int mf = 0; mf < 2; mf++)
#pragma unroll
        for (int nf = 0; nf < 4; nf++)
#pragma unroll
            for (int j = 0; j < 4; j++) acc[mf][nf][j] = 0.f;

    // ---- GEMM 1: v = a2 * Wg ----
#pragma unroll
    for (int kc = 0; kc < 4; kc++) {
        uint32_t ah0[4], ah1[4];
        uint32_t a_off0 = swz128((uint32_t)((m0 + lrow) * 128 + kc * 32 + lc16));
        uint32_t a_off1 = swz128((uint32_t)((m0 + 16 + lrow) * 128 + kc * 32 + lc16));
        ldm4(ah0, sb + A_OFF + a_off0); ldm4(ah1, sb + A_OFF + a_off1);
#pragma unroll
        for (int q = 0; q < 2; q++) {
            uint32_t bh[4];
            uint32_t b_off = swz128((uint32_t)((n0 + 16 * q + lrow) * 128 + kc * 32 + lc16));
            ldm4(bh, sb + b_off);
            mma16816(acc[0][2 * q], ah0, bh[0], bh[2]);
            mma16816(acc[1][2 * q], ah1, bh[0], bh[2]);
            mma16816(acc[0][2 * q + 1], ah0, bh[1], bh[3]);
            mma16816(acc[1][2 * q + 1], ah1, bh[1], bh[3]);
        }
    }
    __syncthreads();

    // ---- epilogue 1: t = u * (v + bg), store fp16 to A smem ----
    const int g = lane >> 2, tg = lane & 3;
#pragma unroll
    for (int mf = 0; mf < 2; mf++) {
        const int mr = m0 + mf * 16 + g;
#pragma unroll
        for (int nf = 0; nf < 4; nf++) {
            const int col = n0 + nf * 8 + 2 * tg;
#pragma unroll
            for (int half = 0; half < 2; half++) {
                const int r = mr + 8 * half;
                const size_t pix = pixbase + r;
                float v0 = acc[mf][nf][2 * half + 0] + bgs[col];
                float v1 = acc[mf][nf][2 * half + 1] + bgs[col + 1];
                float2 u = __half22float2(*(const __half2*)(Uh + pix * 64 + col));
                uint32_t so = swz128((uint32_t)(r * 128 + col * 2));
                *(__half2*)(smem + A_OFF + so) = __floats2half2_rn(v0 * u.x, v1 * u.y);
            }
        }
    }
    __syncthreads();

    // ---- GEMM 2: p2(t) ----
#pragma unroll
    for (int mf = 0; mf < 2; mf++)
#pragma unroll
        for (int nf = 0; nf < 4; nf++)
#pragma unroll
            for (int j = 0; j < 4; j++) acc[mf][nf][j] = 0.f;
#pragma unroll
    for (int kc = 0; kc < 4; kc++) {
        uint32_t ah0[4], ah1[4];
        uint32_t a_off0 = swz128((uint32_t)((m0 + lrow) * 128 + kc * 32 + lc16));
        uint32_t a_off1 = swz128((uint32_t)((m0 + 16 + lrow) * 128 + kc * 32 + lc16));
        ldm4(ah0, sb + A_OFF + a_off0); ldm4(ah1, sb + A_OFF + a_off1);
#pragma unroll
        for (int q = 0; q < 2; q++) {
            uint32_t bh[4];
            uint32_t b_off = swz128((uint32_t)(8192 + (n0 + 16 * q + lrow) * 128 + kc * 32 + lc16));
            ldm4(bh, sb + b_off);
            mma16816(acc[0][2 * q], ah0, bh[0], bh[2]);
            mma16816(acc[1][2 * q], ah1, bh[0], bh[2]);
            mma16816(acc[0][2 * q + 1], ah0, bh[1], bh[3]);
            mma16816(acc[1][2 * q + 1], ah1, bh[1], bh[3]);
        }
    }

    // ---- epilogue 2: + bias + normalized shortcut, LeakyReLU, NCHW ----
#pragma unroll
    for (int mf = 0; mf < 2; mf++) {
        const int mr = m0 + mf * 16 + g;
#pragma unroll
        for (int nf = 0; nf < 4; nf++) {
            const int col = n0 + nf * 8 + 2 * tg;
#pragma unroll
            for (int half = 0; half < 2; half++) {
                const size_t pix = pixbase + mr + 8 * half;
                float v0 = acc[mf][nf][2 * half + 0] + bps[col];
                float v1 = acc[mf][nf][2 * half + 1] + bps[col + 1];
                float2 hh = *(const float2*)(&g_h[pix * 64 + col]);
                v0 += (hh.x - smn[col])     * srd[col];
                v1 += (hh.y - smn[col + 1]) * srd[col + 1];
                v0 = (v0 >= 0.f) ? v0 : 0.2f * v0;
                v1 = (v1 >= 0.f) ? v1 : 0.2f * v1;
                const size_t ppix = pix - bbase;
                dout[(((size_t)(b * 64 + col))     << 16) + ppix] = v0;
                dout[(((size_t)(b * 64 + col + 1)) << 16) + ppix] = v1;
            }
        }
    }
}

// ---------------- instance-norm statistics ---------------------------------
__global__ void k_stats_part() {
    int b = blockIdx.y, s = blockIdx.x;
    int tid = threadIdx.x;
    int c = tid & 63, g = tid >> 6;
    float su = 0.f, sq = 0.f;
    const float* base = g_h + ((size_t)b * PIX + (size_t)s * 2048) * 64;
    for (int p = g; p < 2048; p += 4) {
        float v = base[(size_t)p * 64 + c];
        su += v; sq += v * v;
    }
    __shared__ float bu[256], bq[256];
    bu[tid] = su; bq[tid] = sq;
    __syncthreads();
    if (g == 0) {
        su = bu[c] + bu[64 + c] + bu[128 + c] + bu[192 + c];
        sq = bq[c] + bq[64 + c] + bq[128 + c] + bq[192 + c];
        g_part[((b * 32 + s) * 64 + c) * 2 + 0] = su;
        g_part[((b * 32 + s) * 64 + c) * 2 + 1] = sq;
    }
}
__global__ void k_stats_final() {
    int tid = threadIdx.x;
    int b = tid >> 6, c = tid & 63;
    float su = 0.f, sq = 0.f;
    for (int s = 0; s < 32; s++) {
        su += g_part[((b * 32 + s) * 64 + c) * 2 + 0];
        sq += g_part[((b * 32 + s) * 64 + c) * 2 + 1];
    }
    float m   = su * (1.f / 65536.f);
    float var = sq * (1.f / 65536.f) - m * m;
    g_stats[tid]       = m;
    g_stats[256 + tid] = rsqrtf(var + 1e-5f);
}

// ---------------- deformable depthwise conv (half2 SIMD, fp16 gather) ------
template <int K, int OSTR, int PAD, int DIL>
__global__ void __launch_bounds__(256) k_deform(const __half* __restrict__ in,
                                                const __half* __restrict__ off,
                                                const float* __restrict__ dw,
                                                __half* __restrict__ obh) {
    constexpr int KK = K * K;
    __shared__ __align__(16) __half2 ws2[KK * 32];
    int tid = threadIdx.x;
    for (int i = tid; i < KK * 32; i += 256) {
        int k = i >> 5, cp = i & 31;
        ws2[i] = __floats2half2_rn(dw[(2 * cp) * KK + k], dw[(2 * cp + 1) * KK + k]);
    }
    __syncthreads();
    int gp = blockIdx.x * 32 + (tid >> 3);
    int c0 = (tid & 7) * 8;
    int b = gp >> 16, p = gp & 65535;
    int y = p >> 8, x = p & 255;
    const __half* offp = off + (size_t)gp * OSTR;
    const __half* inb = in + (((size_t)b) << 16) * 64;
    __half2 a2[4];
#pragma unroll
    for (int j = 0; j < 4; j++) a2[j] = __floats2half2_rn(0.f, 0.f);
#pragma unroll 1
    for (int k = 0; k < KK; k++) {
        float2 o2 = __half22float2(*(const __half2*)(offp + 2 * k));
        float py = (float)(y - PAD + DIL * (k / K)) + o2.x;
        float px = (float)(x - PAD + DIL * (k % K)) + o2.y;
        float y0f = floorf(py), x0f = floorf(px);
        float fy = py - y0f, fx = px - x0f;
        int y0 = (int)y0f, x0 = (int)x0f;
        bool yv0 = (y0 >= 0) & (y0 <= 255);
        bool yv1 = (y0 >= -1) & (y0 <= 254);
        bool xv0 = (x0 >= 0) & (x0 <= 255);
        bool xv1 = (x0 >= -1) & (x0 <= 254);
        __half2 w00 = __float2half2_rn((1.f - fy) * (1.f - fx));
        __half2 w01 = __float2half2_rn((1.f - fy) * fx);
        __half2 w10 = __float2half2_rn(fy * (1.f - fx));
        __half2 w11 = __float2half2_rn(fy * fx);
        __half2 s[4];
#pragma unroll
        for (int j = 0; j < 4; j++) s[j] = __floats2half2_rn(0.f, 0.f);
        auto addc = [&](int yy, int xx, __half2 wgt) {
            uint4 v = *(const uint4*)(inb + ((size_t)(yy * 256 + xx)) * 64 + c0);
            const __half2* hp = (const __half2*)&v;
#pragma unroll
            for (int j = 0; j < 4; j++) s[j] = __hfma2(hp[j], wgt, s[j]);
        };
        if (yv0) {
            if (xv0) addc(y0, x0, w00);
            if (xv1) addc(y0, x0 + 1, w01);
        }
        if (yv1) {
            if (xv0) addc(y0 + 1, x0, w10);
            if (xv1) addc(y0 + 1, x0 + 1, w11);
        }
        const __half2* wk = ws2 + k * 32 + (c0 >> 1);
#pragma unroll
        for (int j = 0; j < 4; j++) a2[j] = __hfma2(s[j], wk[j], a2[j]);
    }
    *(uint4*)(obh + (size_t)gp * 64 + c0) = *(uint4*)a2;
}

// ---------------------------------------------------------------------------
extern "C" void kernel_launch(void* const* d_in, const int* in_sizes, int n_in,
                              void* d_out, int out_size) {
    const float* x      = (const float*)d_in[0];
    const float* conv_w = (const float*)d_in[1];
    const float* p1_w   = (const float*)d_in[2];
    const float* p1_b   = (const float*)d_in[3];
    const float* off0_w = (const float*)d_in[4];
    const float* off0_b = (const float*)d_in[5];
    const float* dw0_w  = (const float*)d_in[6];
    const float* offs_w = (const float*)d_in[7];
    const float* offs_b = (const float*)d_in[8];
    const float* dws_w  = (const float*)d_in[9];
    const float* g1_w   = (const float*)d_in[10];
    const float* g1_b   = (const float*)d_in[11];
    const float* p2_w   = (const float*)d_in[12];
    const float* p2_b   = (const float*)d_in[13];
    float* out = (float*)d_out;

    float *h, *bp1;
    __half *offb, *bfh, *bfl, *b2h;
    __half *w3h, *w3l, *w5h, *w7h, *wp1h, *wg1h, *wp2h;
    cudaGetSymbolAddress((void**)&h,    g_h);
    cudaGetSymbolAddress((void**)&offb, g_off);
    cudaGetSymbolAddress((void**)&bp1,  g_bp1);
    cudaGetSymbolAddress((void**)&bfh,  g_bfh);
    cudaGetSymbolAddress((void**)&bfl,  g_bfl);
    cudaGetSymbolAddress((void**)&b2h,  g_b2h);
    cudaGetSymbolAddress((void**)&w3h,  g_w3h);
    cudaGetSymbolAddress((void**)&w3l,  g_w3l);
    cudaGetSymbolAddress((void**)&w5h,  g_w5h);
    cudaGetSymbolAddress((void**)&w7h,  g_w7h);
    cudaGetSymbolAddress((void**)&wp1h, g_wp1h);
    cudaGetSymbolAddress((void**)&wg1h, g_wg1h);
    cudaGetSymbolAddress((void**)&wp2h, g_wp2h);

    const int SM_3 = 2 * 16384 + 2 * 17408 + 512;   // 68352
    const int SM_5 = 2 * 8192 + 17408 + 512;        // 34304
    const int SM_7 = 2 * 14336 + 19456 + 512;       // 48640
    const int SM_P = 8192 + 16384 + 1024;           // 25600
    const int SM_F = 16384 + 16384 + 1024;          // 33792
    cudaFuncSetAttribute((const void*)k_mmaconv<64, 64, 4, 3, 1, 1, false, 64, 3, 0>,
                         cudaFuncAttributeMaxDynamicSharedMemorySize, SM_3);
    cudaFuncSetAttribute((const void*)k_mmaconv<50, 64, 4, 5, 2, 1, true, 64, 1, 1>,
                         cudaFuncAttributeMaxDynamicSharedMemorySize, SM_5);
    cudaFuncSetAttribute((const void*)k_mmaconv<98, 112, 7, 7, 9, 3, true, 112, 1, 1>,
                         cudaFuncAttributeMaxDynamicSharedMemorySize, SM_7);
    cudaFuncSetAttribute((const void*)k_p1g,
                         cudaFuncAttributeMaxDynamicSharedMemorySize, SM_P);
    cudaFuncSetAttribute((const void*)k_g1p2,
                         cudaFuncAttributeMaxDynamicSharedMemorySize, SM_F);

    k_x2bf<<<dim3(PIX / 32, CH / 32, BB), dim3(32, 8)>>>(x);
    k_prepw<<<(9  * 64  * 64 + 255) / 256, 256>>>(conv_w, w3h, w3l, 64, 64, 9);
    k_prepw<<<(25 * 64  * 64 + 255) / 256, 256>>>(off0_w, w5h, nullptr, 50, 64, 25);
    k_prepw<<<(49 * 112 * 64 + 255) / 256, 256>>>(offs_w, w7h, nullptr, 98, 112, 49);
    k_prepw<<<16, 256>>>(g1_w, wg1h, nullptr, 64, 64, 1);
    k_prepw<<<16, 256>>>(p2_w, wp2h, nullptr, 64, 64, 1);

    dim3 mg(IH * 2, BB);

    // conv3 (3-pass): x hi/lo -> g_h fp32 + h-hi (b2h)
    k_mmaconv<64, 64, 4, 3, 1, 1, false, 64, 3, 0>
        <<<mg, 256, SM_3>>>(bfh, bfl, w3h, w3l, nullptr, (void*)h, b2h);
    k_stats_part<<<dim3(32, BB), 256>>>();
    k_stats_final<<<1, 256>>>();
    k_prepp1<<<256, 64>>>(p1_w, p1_b);

    // p1 + gelu: h-hi -> u-hi (bfh; x dead)
    k_p1g<<<mg, 256, SM_P>>>(b2h, wp1h, bp1, bfh);

    // conv5 offsets (fp16 out): u-hi -> g_off
    k_mmaconv<50, 64, 4, 5, 2, 1, true, 64, 1, 1>
        <<<mg, 256, SM_5>>>(bfh, nullptr, w5h, nullptr, off0_b, (void*)offb, nullptr);
    // deform5: sample u-hi -> a1-hi (b2h; h-hi dead)
    k_deform<5, 64, 2, 1><<<NPIX / 32, 256>>>(bfh, offb, dw0_w, b2h);

    // conv7 offsets (fp16 out): a1-hi -> g_off
    k_mmaconv<98, 112, 7, 7, 9, 3, true, 112, 1, 1>
        <<<mg, 256, SM_7>>>(b2h, nullptr, w7h, nullptr, offs_b, (void*)offb, nullptr);
    // deform7: sample a1-hi -> a2-hi (bfl; x-lo dead)
    k_deform<7, 112, 9, 3><<<NPIX / 32, 256>>>(b2h, offb, dws_w, bfl);

    // fused g1 -> u-mul -> p2 -> shortcut + LeakyReLU -> NCHW
    k_g1p2<<<mg, 256, SM_F>>>(bfl, bfh, wg1h, wp2h, g1_b, p2_b, out);
}